// round 2
// baseline (speedup 1.0000x reference)
#include <cuda_runtime.h>
#include <math.h>

#define BB 64
#define LL 512
#define RR 512
#define HH 512
#define DD 256

// Scratch (device-global: no allocations allowed in kernel_launch)
__device__ float g_lt[(size_t)BB * LL * DD];          // tanh(lt@W)*diag   33.5 MB
__device__ float g_rt[(size_t)BB * RR * DD];          // tanh(rt@W)        33.5 MB
__device__ float g_sc[(size_t)BB * LL * RR];          // scores            67 MB

// ---------------------------------------------------------------------------
// Projection GEMM: C[m,d] = tanh(sum_h A[m,h] * W[h,d]) * (diag ? diag[d] : 1)
// 128x128 tile, BK=8, 256 threads, 8x8 microtile.
// ---------------------------------------------------------------------------
template <bool USE_DIAG>
__global__ __launch_bounds__(256) void proj_kernel(
    const float* __restrict__ A, const float* __restrict__ Wm,
    const float* __restrict__ diag, float* __restrict__ C)
{
    __shared__ float As[8][128];
    __shared__ float Bs[8][128];

    const int tid = threadIdx.x;
    const long bm = (long)blockIdx.y * 128;
    const int  bn = blockIdx.x * 128;

    const int a_row = tid >> 1;            // 0..127
    const int a_col = (tid & 1) * 4;       // 0 or 4
    const int b_row = tid >> 5;            // 0..7
    const int b_col = (tid & 31) * 4;      // 0..124

    const int tx = tid & 15;               // output col group
    const int ty = tid >> 4;               // output row group

    float acc[8][8];
    #pragma unroll
    for (int i = 0; i < 8; i++)
        #pragma unroll
        for (int j = 0; j < 8; j++) acc[i][j] = 0.f;

    const float* Aptr = A + (bm + a_row) * (long)HH + a_col;

    for (int k0 = 0; k0 < HH; k0 += 8) {
        float4 av = *reinterpret_cast<const float4*>(Aptr + k0);
        float4 bv = *reinterpret_cast<const float4*>(&Wm[(long)(k0 + b_row) * DD + bn + b_col]);
        __syncthreads();
        As[a_col + 0][a_row] = av.x;
        As[a_col + 1][a_row] = av.y;
        As[a_col + 2][a_row] = av.z;
        As[a_col + 3][a_row] = av.w;
        *reinterpret_cast<float4*>(&Bs[b_row][b_col]) = bv;
        __syncthreads();

        #pragma unroll
        for (int k = 0; k < 8; ++k) {
            float af[8], bf[8];
            *reinterpret_cast<float4*>(af)     = *reinterpret_cast<const float4*>(&As[k][ty * 8]);
            *reinterpret_cast<float4*>(af + 4) = *reinterpret_cast<const float4*>(&As[k][ty * 8 + 4]);
            *reinterpret_cast<float4*>(bf)     = *reinterpret_cast<const float4*>(&Bs[k][tx * 8]);
            *reinterpret_cast<float4*>(bf + 4) = *reinterpret_cast<const float4*>(&Bs[k][tx * 8 + 4]);
            #pragma unroll
            for (int i = 0; i < 8; i++)
                #pragma unroll
                for (int j = 0; j < 8; j++)
                    acc[i][j] = fmaf(af[i], bf[j], acc[i][j]);
        }
    }

    #pragma unroll
    for (int i = 0; i < 8; i++) {
        long m = bm + ty * 8 + i;
        #pragma unroll
        for (int j = 0; j < 8; j++) {
            int n = bn + tx * 8 + j;
            float v = tanhf(acc[i][j]);
            if (USE_DIAG) v *= diag[n];
            C[m * DD + n] = v;
        }
    }
}

// ---------------------------------------------------------------------------
// Batched scores GEMM (NT): S[b][l,r] = sum_d g_lt[b][l,d] * g_rt[b][r,d]
// 128x128 tile, BK=8. grid = (R/128, L/128, B)
// ---------------------------------------------------------------------------
__global__ __launch_bounds__(256) void scores_kernel()
{
    __shared__ float As[8][128];
    __shared__ float Bs[8][128];

    const int b   = blockIdx.z;
    const float* Lt = g_lt + (size_t)b * LL * DD;
    const float* Rt = g_rt + (size_t)b * RR * DD;
    float*       S  = g_sc + (size_t)b * LL * RR;

    const int tid = threadIdx.x;
    const int bm = blockIdx.y * 128;   // l tile
    const int bn = blockIdx.x * 128;   // r tile

    const int row = tid >> 1;          // 0..127
    const int col = (tid & 1) * 4;     // 0 or 4

    const int tx = tid & 15;
    const int ty = tid >> 4;

    float acc[8][8];
    #pragma unroll
    for (int i = 0; i < 8; i++)
        #pragma unroll
        for (int j = 0; j < 8; j++) acc[i][j] = 0.f;

    const float* Ap = Lt + (long)(bm + row) * DD + col;
    const float* Bp = Rt + (long)(bn + row) * DD + col;

    for (int k0 = 0; k0 < DD; k0 += 8) {
        float4 av = *reinterpret_cast<const float4*>(Ap + k0);
        float4 bv = *reinterpret_cast<const float4*>(Bp + k0);
        __syncthreads();
        As[col + 0][row] = av.x;  As[col + 1][row] = av.y;
        As[col + 2][row] = av.z;  As[col + 3][row] = av.w;
        Bs[col + 0][row] = bv.x;  Bs[col + 1][row] = bv.y;
        Bs[col + 2][row] = bv.z;  Bs[col + 3][row] = bv.w;
        __syncthreads();

        #pragma unroll
        for (int k = 0; k < 8; ++k) {
            float af[8], bf[8];
            *reinterpret_cast<float4*>(af)     = *reinterpret_cast<const float4*>(&As[k][ty * 8]);
            *reinterpret_cast<float4*>(af + 4) = *reinterpret_cast<const float4*>(&As[k][ty * 8 + 4]);
            *reinterpret_cast<float4*>(bf)     = *reinterpret_cast<const float4*>(&Bs[k][tx * 8]);
            *reinterpret_cast<float4*>(bf + 4) = *reinterpret_cast<const float4*>(&Bs[k][tx * 8 + 4]);
            #pragma unroll
            for (int i = 0; i < 8; i++)
                #pragma unroll
                for (int j = 0; j < 8; j++)
                    acc[i][j] = fmaf(af[i], bf[j], acc[i][j]);
        }
    }

    #pragma unroll
    for (int i = 0; i < 8; i++) {
        int m = bm + ty * 8 + i;
        float* srow = S + (long)m * RR + bn + tx * 8;
        float4 v0 = make_float4(acc[i][0], acc[i][1], acc[i][2], acc[i][3]);
        float4 v1 = make_float4(acc[i][4], acc[i][5], acc[i][6], acc[i][7]);
        *reinterpret_cast<float4*>(srow)     = v0;
        *reinterpret_cast<float4*>(srow + 4) = v1;
    }
}

// ---------------------------------------------------------------------------
// Row softmax over R=512. One block (256 threads) per (b,l) row.
// ---------------------------------------------------------------------------
__global__ __launch_bounds__(256) void softmax_kernel(float* __restrict__ out)
{
    const float* s = g_sc + (size_t)blockIdx.x * RR;
    float*       o = out + (size_t)blockIdx.x * RR;
    const int t = threadIdx.x;

    float v0 = s[t];
    float v1 = s[t + 256];

    // max reduce
    float m = fmaxf(v0, v1);
    #pragma unroll
    for (int off = 16; off; off >>= 1)
        m = fmaxf(m, __shfl_xor_sync(0xffffffffu, m, off));
    __shared__ float red[8];
    if ((t & 31) == 0) red[t >> 5] = m;
    __syncthreads();
    if (t < 8) {
        float mm = red[t];
        #pragma unroll
        for (int off = 4; off; off >>= 1)
            mm = fmaxf(mm, __shfl_xor_sync(0xffu, mm, off));
        red[t] = mm;
    }
    __syncthreads();
    m = red[0];

    float e0 = expf(v0 - m);
    float e1 = expf(v1 - m);

    // sum reduce
    float ssum = e0 + e1;
    #pragma unroll
    for (int off = 16; off; off >>= 1)
        ssum += __shfl_xor_sync(0xffffffffu, ssum, off);
    __shared__ float red2[8];
    if ((t & 31) == 0) red2[t >> 5] = ssum;
    __syncthreads();
    if (t < 8) {
        float z = red2[t];
        #pragma unroll
        for (int off = 4; off; off >>= 1)
            z += __shfl_xor_sync(0xffu, z, off);
        red2[t] = z;
    }
    __syncthreads();
    float inv = 1.0f / red2[0];

    o[t]       = e0 * inv;
    o[t + 256] = e1 * inv;
}

// ---------------------------------------------------------------------------
extern "C" void kernel_launch(void* const* d_in, const int* in_sizes, int n_in,
                              void* d_out, int out_size)
{
    const float* lt   = (const float*)d_in[0];   // (B, L, H)
    const float* rt   = (const float*)d_in[1];   // (B, R, H)
    const float* Wm   = (const float*)d_in[2];   // (H, D)
    const float* diag = (const float*)d_in[3];   // (1, 1, D)
    float* out = (float*)d_out;                  // (B, L, R)

    float *p_lt, *p_rt;
    cudaGetSymbolAddress((void**)&p_lt, g_lt);
    cudaGetSymbolAddress((void**)&p_rt, g_rt);

    // Projections: M = B*L = B*R = 32768, N = D = 256, K = H = 512
    dim3 projGrid(DD / 128, (BB * LL) / 128);
    proj_kernel<true ><<<projGrid, 256>>>(lt, Wm, diag, p_lt);
    proj_kernel<false><<<projGrid, 256>>>(rt, Wm, nullptr, p_rt);

    // Batched scores GEMM
    dim3 scGrid(RR / 128, LL / 128, BB);
    scores_kernel<<<scGrid, 256>>>();

    // Softmax into output
    softmax_kernel<<<BB * LL, 256>>>(out);
}

// round 4
// speedup vs baseline: 2.3292x; 2.3292x over previous
#include <cuda_runtime.h>
#include <cstdint>
#include <math.h>

#define BB 64
#define SEQ 512
#define HH 512
#define DD 256

// Scratch (device globals: no allocation allowed in kernel_launch)
__device__ float g_lt[(size_t)BB * SEQ * DD];   // tf32(tanh(lt@W)*diag)
__device__ float g_rt[(size_t)BB * SEQ * DD];   // tf32(tanh(rt@W))
__device__ float g_wt[(size_t)DD * HH];         // tf32(W^T)  (D,H)
__device__ float g_sc[(size_t)BB * SEQ * SEQ];  // raw scores

// ---------------------------------------------------------------------------
__device__ __forceinline__ uint32_t f2tf32(float f) {
    uint32_t r; asm("cvt.rna.tf32.f32 %0, %1;" : "=r"(r) : "f"(f)); return r;
}
__device__ __forceinline__ uint32_t smem_u32(const void* p) {
    uint32_t a;
    asm("{ .reg .u64 t; cvta.to.shared.u64 t, %1; cvt.u32.u64 %0, t; }" : "=r"(a) : "l"(p));
    return a;
}
__device__ __forceinline__ void cp16(uint32_t s, const void* g) {
    asm volatile("cp.async.cg.shared.global [%0], [%1], 16;" :: "r"(s), "l"(g));
}
#define CP_COMMIT() asm volatile("cp.async.commit_group;" ::: "memory")
#define CP_WAIT(n)  asm volatile("cp.async.wait_group %0;" :: "n"(n) : "memory")

// D[16x8] += A[16x8] * B[8x8]  (tf32, row.col)
__device__ __forceinline__ void mma8(float* d, const uint32_t* a, const uint32_t* b) {
    asm volatile(
        "mma.sync.aligned.m16n8k8.row.col.f32.tf32.tf32.f32 "
        "{%0,%1,%2,%3}, {%4,%5,%6,%7}, {%8,%9}, {%0,%1,%2,%3};"
        : "+f"(d[0]), "+f"(d[1]), "+f"(d[2]), "+f"(d[3])
        : "r"(a[0]), "r"(a[1]), "r"(a[2]), "r"(a[3]), "r"(b[0]), "r"(b[1]));
}

#define PITCH 20   // floats per smem row (16 data + 4 pad): conflict-free frag loads

// ---------------------------------------------------------------------------
// Unified tensor-core GEMM.
//   PROJ=true : C[128y..][128x..] = tf32(tanh(A@B^T) [*diag]), A:(M,KD) B:(g_wt: D,KD)
//   PROJ=false: batched scores, A=g_lt B=g_rt per blockIdx.z, C=g_sc raw f32
// CTA tile 128x128xKD, BK=16, 8 warps (2 M x 4 N), warp tile 64x32.
// ---------------------------------------------------------------------------
template <int KD, bool CVT_A, bool PROJ, bool USE_DIAG>
__global__ __launch_bounds__(256, 1) void gemm_tc(
    const float* __restrict__ A0, const float* __restrict__ B0,
    const float* __restrict__ diag, float* __restrict__ C0)
{
    __shared__ float As[2][128 * PITCH];
    __shared__ float Bs[2][128 * PITCH];

    const int tid = threadIdx.x, lane = tid & 31, wid = tid >> 5;
    const int gid = lane >> 2, tig = lane & 3;
    const int wm = wid & 1, wn = wid >> 1;

    const float* A; const float* B; float* C; int ldc;
    if (PROJ) {
        A = A0 + (size_t)blockIdx.y * 128 * KD;
        B = B0 + (size_t)blockIdx.x * 128 * KD;
        C = C0 + (size_t)blockIdx.y * 128 * DD + blockIdx.x * 128;
        ldc = DD;
    } else {
        const size_t bo = (size_t)blockIdx.z;
        A = A0 + bo * SEQ * KD + (size_t)blockIdx.y * 128 * KD;
        B = B0 + bo * SEQ * KD + (size_t)blockIdx.x * 128 * KD;
        C = C0 + bo * SEQ * SEQ + (size_t)blockIdx.y * 128 * SEQ + blockIdx.x * 128;
        ldc = SEQ;
    }

    float acc[4][4][4];
    #pragma unroll
    for (int mt = 0; mt < 4; mt++)
        #pragma unroll
        for (int nt = 0; nt < 4; nt++)
            #pragma unroll
            for (int c = 0; c < 4; c++) acc[mt][nt][c] = 0.f;

    // tile loader: 128 rows x 16 floats each for A and B (4x 16B chunks/row)
    const int r_ld0 = tid >> 2;              // rows for chunk j=0: 0..63
    const int kq_ld = tid & 3;
    auto load_tile = [&](int kt, int buf) {
        const int kb = kt * 16;
        #pragma unroll
        for (int j = 0; j < 2; j++) {
            const int r = r_ld0 + j * 64;
            cp16(smem_u32(&As[buf][r * PITCH + kq_ld * 4]),
                 A + (size_t)r * KD + kb + kq_ld * 4);
            cp16(smem_u32(&Bs[buf][r * PITCH + kq_ld * 4]),
                 B + (size_t)r * KD + kb + kq_ld * 4);
        }
        CP_COMMIT();
    };

    constexpr int NK = KD / 16;
    load_tile(0, 0);

    #pragma unroll 1
    for (int kt = 0; kt < NK; kt++) {
        const int cur = kt & 1;
        if (kt + 1 < NK) { load_tile(kt + 1, cur ^ 1); CP_WAIT(1); }
        else             { CP_WAIT(0); }
        __syncthreads();

        #pragma unroll
        for (int ks = 0; ks < 2; ks++) {
            uint32_t af[4][4], bf[4][2];
            const int c0 = ks * 8 + tig;
            #pragma unroll
            for (int mt = 0; mt < 4; mt++) {
                const int r = (wm * 64 + mt * 16 + gid) * PITCH;
                float x0 = As[cur][r + c0];
                float x1 = As[cur][r + 8 * PITCH + c0];
                float x2 = As[cur][r + c0 + 4];
                float x3 = As[cur][r + 8 * PITCH + c0 + 4];
                if (CVT_A) {
                    af[mt][0] = f2tf32(x0); af[mt][1] = f2tf32(x1);
                    af[mt][2] = f2tf32(x2); af[mt][3] = f2tf32(x3);
                } else {
                    af[mt][0] = __float_as_uint(x0); af[mt][1] = __float_as_uint(x1);
                    af[mt][2] = __float_as_uint(x2); af[mt][3] = __float_as_uint(x3);
                }
            }
            #pragma unroll
            for (int nt = 0; nt < 4; nt++) {
                const int r = (wn * 32 + nt * 8 + gid) * PITCH;
                bf[nt][0] = __float_as_uint(Bs[cur][r + c0]);
                bf[nt][1] = __float_as_uint(Bs[cur][r + c0 + 4]);
            }
            #pragma unroll
            for (int mt = 0; mt < 4; mt++)
                #pragma unroll
                for (int nt = 0; nt < 4; nt++)
                    mma8(acc[mt][nt], af[mt], bf[nt]);
        }
        __syncthreads();
    }

    // ---- epilogue ----
    #pragma unroll
    for (int mt = 0; mt < 4; mt++) {
        const int row0 = wm * 64 + mt * 16 + gid;
        #pragma unroll
        for (int nt = 0; nt < 4; nt++) {
            const int col = wn * 32 + nt * 8 + tig * 2;
            if (PROJ) {
                float d0 = 1.f, d1 = 1.f;
                if (USE_DIAG) {
                    const int gcol = blockIdx.x * 128 + col;
                    d0 = __ldg(diag + gcol); d1 = __ldg(diag + gcol + 1);
                }
                float2 v0, v1;
                v0.x = __uint_as_float(f2tf32(tanhf(acc[mt][nt][0]) * d0));
                v0.y = __uint_as_float(f2tf32(tanhf(acc[mt][nt][1]) * d1));
                v1.x = __uint_as_float(f2tf32(tanhf(acc[mt][nt][2]) * d0));
                v1.y = __uint_as_float(f2tf32(tanhf(acc[mt][nt][3]) * d1));
                *reinterpret_cast<float2*>(C + (size_t)row0 * ldc + col) = v0;
                *reinterpret_cast<float2*>(C + (size_t)(row0 + 8) * ldc + col) = v1;
            } else {
                float2 v0 = make_float2(acc[mt][nt][0], acc[mt][nt][1]);
                float2 v1 = make_float2(acc[mt][nt][2], acc[mt][nt][3]);
                *reinterpret_cast<float2*>(C + (size_t)row0 * ldc + col) = v0;
                *reinterpret_cast<float2*>(C + (size_t)(row0 + 8) * ldc + col) = v1;
            }
        }
    }
}

// ---------------------------------------------------------------------------
// W transpose (H,D) -> (D,H), pre-rounded to tf32.
// ---------------------------------------------------------------------------
__global__ void transpose_w(const float* __restrict__ W, float* __restrict__ Wt) {
    __shared__ float t[32][33];
    const int d0 = blockIdx.x * 32, h0 = blockIdx.y * 32;
    for (int i = threadIdx.y; i < 32; i += 8)
        t[i][threadIdx.x] = W[(size_t)(h0 + i) * DD + d0 + threadIdx.x];
    __syncthreads();
    for (int i = threadIdx.y; i < 32; i += 8)
        Wt[(size_t)(d0 + i) * HH + h0 + threadIdx.x] =
            __uint_as_float(f2tf32(t[threadIdx.x][i]));
}

// ---------------------------------------------------------------------------
// Softmax: 2 rows per 256-thread block; 128 threads/row, float4 per thread.
// ---------------------------------------------------------------------------
__global__ __launch_bounds__(256) void softmax_kernel(float* __restrict__ out) {
    const int half = threadIdx.x >> 7;
    const int t = threadIdx.x & 127;
    const int w = t >> 5;
    const size_t row = (size_t)blockIdx.x * 2 + half;

    float4 v = reinterpret_cast<const float4*>(g_sc + row * SEQ)[t];

    float m = fmaxf(fmaxf(v.x, v.y), fmaxf(v.z, v.w));
    #pragma unroll
    for (int off = 16; off; off >>= 1)
        m = fmaxf(m, __shfl_xor_sync(0xffffffffu, m, off));
    __shared__ float red[2][4];
    if ((t & 31) == 0) red[half][w] = m;
    __syncthreads();
    m = fmaxf(fmaxf(red[half][0], red[half][1]), fmaxf(red[half][2], red[half][3]));

    float4 e;
    e.x = __expf(v.x - m); e.y = __expf(v.y - m);
    e.z = __expf(v.z - m); e.w = __expf(v.w - m);
    float s = e.x + e.y + e.z + e.w;
    #pragma unroll
    for (int off = 16; off; off >>= 1)
        s += __shfl_xor_sync(0xffffffffu, s, off);
    __shared__ float red2[2][4];
    if ((t & 31) == 0) red2[half][w] = s;
    __syncthreads();
    s = red2[half][0] + red2[half][1] + red2[half][2] + red2[half][3];

    const float inv = 1.f / s;
    float4 o = make_float4(e.x * inv, e.y * inv, e.z * inv, e.w * inv);
    reinterpret_cast<float4*>(out + row * SEQ)[t] = o;
}

// ---------------------------------------------------------------------------
extern "C" void kernel_launch(void* const* d_in, const int* in_sizes, int n_in,
                              void* d_out, int out_size)
{
    const float* lt = (const float*)d_in[0];   // (B, L, H)
    const float* rt = (const float*)d_in[1];   // (B, R, H)
    const float* W  = (const float*)d_in[2];   // (H, D)
    const float* dg = (const float*)d_in[3];   // (1, 1, D)
    float* out = (float*)d_out;                // (B, L, R)

    float *p_lt, *p_rt, *p_wt, *p_sc;
    cudaGetSymbolAddress((void**)&p_lt, g_lt);
    cudaGetSymbolAddress((void**)&p_rt, g_rt);
    cudaGetSymbolAddress((void**)&p_wt, g_wt);
    cudaGetSymbolAddress((void**)&p_sc, g_sc);

    transpose_w<<<dim3(DD / 32, HH / 32), dim3(32, 8)>>>(W, p_wt);

    // Projections: M = 32768, N = 256, K = 512
    gemm_tc<HH, true, true, true ><<<dim3(2, 256), 256>>>(lt, p_wt, dg, p_lt);
    gemm_tc<HH, true, true, false><<<dim3(2, 256), 256>>>(rt, p_wt, nullptr, p_rt);

    // Scores: per batch 512x512x256
    gemm_tc<DD, false, false, false><<<dim3(4, 4, BB), 256>>>(p_lt, p_rt, nullptr, p_sc);

    // Softmax
    softmax_kernel<<<(BB * SEQ) / 2, 256>>>(out);
}

// round 6
// speedup vs baseline: 2.4529x; 1.0531x over previous
#include <cuda_runtime.h>
#include <cstdint>
#include <math.h>

#define BB 64
#define SEQ 512
#define HH 512
#define DD 256

// Scratch (device globals: no allocation allowed in kernel_launch)
__device__ float g_lt[(size_t)BB * SEQ * DD];   // tf32(tanh(lt@W)*diag)
__device__ float g_rt[(size_t)BB * SEQ * DD];   // tf32(tanh(rt@W))
__device__ float g_wt[(size_t)DD * HH];         // tf32(W^T)  (D,H)

// ---------------------------------------------------------------------------
__device__ __forceinline__ uint32_t f2tf32(float f) {
    uint32_t r; asm("cvt.rna.tf32.f32 %0, %1;" : "=r"(r) : "f"(f)); return r;
}
__device__ __forceinline__ uint32_t smem_u32(const void* p) {
    uint32_t a;
    asm("{ .reg .u64 t; cvta.to.shared.u64 t, %1; cvt.u32.u64 %0, t; }" : "=r"(a) : "l"(p));
    return a;
}
__device__ __forceinline__ void cp16(uint32_t s, const void* g) {
    asm volatile("cp.async.cg.shared.global [%0], [%1], 16;" :: "r"(s), "l"(g));
}
#define CP_COMMIT() asm volatile("cp.async.commit_group;" ::: "memory")
#define CP_WAIT(n)  asm volatile("cp.async.wait_group %0;" :: "n"(n) : "memory")

// D[16x8] += A[16x8] * B[8x8]  (tf32, row.col)
__device__ __forceinline__ void mma8(float* d, const uint32_t* a, const uint32_t* b) {
    asm volatile(
        "mma.sync.aligned.m16n8k8.row.col.f32.tf32.tf32.f32 "
        "{%0,%1,%2,%3}, {%4,%5,%6,%7}, {%8,%9}, {%0,%1,%2,%3};"
        : "+f"(d[0]), "+f"(d[1]), "+f"(d[2]), "+f"(d[3])
        : "r"(a[0]), "r"(a[1]), "r"(a[2]), "r"(a[3]), "r"(b[0]), "r"(b[1]));
}

#define PITCH 20   // floats per smem row (16 data + 4 pad)

// ---------------------------------------------------------------------------
// Projection GEMM (both lt and rt in one launch).
//   blockIdx.y < 256 : lt tile, apply diag;  >= 256 : rt tile, no diag.
// CTA tile 128x128, K=512, BK=16, 8 warps (2Mx4N), warp tile 64x32.
// ---------------------------------------------------------------------------
__global__ __launch_bounds__(256, 2) void proj_tc(
    const float* __restrict__ lt, const float* __restrict__ rt,
    const float* __restrict__ diag,
    float* __restrict__ Clt, float* __restrict__ Crt)
{
    __shared__ float As[2][128 * PITCH];
    __shared__ float Bs[2][128 * PITCH];

    const int tid = threadIdx.x, lane = tid & 31, wid = tid >> 5;
    const int gid = lane >> 2, tig = lane & 3;
    const int wm = wid & 1, wn = wid >> 1;

    const bool is_lt = blockIdx.y < 256;
    const int my = is_lt ? blockIdx.y : (blockIdx.y - 256);
    const float* A = (is_lt ? lt : rt) + (size_t)my * 128 * HH;
    const float* B = g_wt + (size_t)blockIdx.x * 128 * HH;
    float* C = (is_lt ? Clt : Crt) + (size_t)my * 128 * DD + blockIdx.x * 128;

    float acc[4][4][4];
    #pragma unroll
    for (int mt = 0; mt < 4; mt++)
        #pragma unroll
        for (int nt = 0; nt < 4; nt++)
            #pragma unroll
            for (int c = 0; c < 4; c++) acc[mt][nt][c] = 0.f;

    const int r_ld0 = tid >> 2;
    const int kq_ld = tid & 3;
    auto load_tile = [&](int kt, int buf) {
        const int kb = kt * 16;
        #pragma unroll
        for (int j = 0; j < 2; j++) {
            const int r = r_ld0 + j * 64;
            cp16(smem_u32(&As[buf][r * PITCH + kq_ld * 4]),
                 A + (size_t)r * HH + kb + kq_ld * 4);
            cp16(smem_u32(&Bs[buf][r * PITCH + kq_ld * 4]),
                 B + (size_t)r * HH + kb + kq_ld * 4);
        }
        CP_COMMIT();
    };

    constexpr int NK = HH / 16;
    load_tile(0, 0);

    #pragma unroll 1
    for (int kt = 0; kt < NK; kt++) {
        const int cur = kt & 1;
        if (kt + 1 < NK) { load_tile(kt + 1, cur ^ 1); CP_WAIT(1); }
        else             { CP_WAIT(0); }
        __syncthreads();

        #pragma unroll
        for (int ks = 0; ks < 2; ks++) {
            uint32_t af[4][4], bf[4][2];
            const int c0 = ks * 8 + tig;
            #pragma unroll
            for (int mt = 0; mt < 4; mt++) {
                const int r = (wm * 64 + mt * 16 + gid) * PITCH;
                af[mt][0] = f2tf32(As[cur][r + c0]);
                af[mt][1] = f2tf32(As[cur][r + 8 * PITCH + c0]);
                af[mt][2] = f2tf32(As[cur][r + c0 + 4]);
                af[mt][3] = f2tf32(As[cur][r + 8 * PITCH + c0 + 4]);
            }
            #pragma unroll
            for (int nt = 0; nt < 4; nt++) {
                const int r = (wn * 32 + nt * 8 + gid) * PITCH;
                bf[nt][0] = __float_as_uint(Bs[cur][r + c0]);
                bf[nt][1] = __float_as_uint(Bs[cur][r + c0 + 4]);
            }
            #pragma unroll
            for (int mt = 0; mt < 4; mt++)
                #pragma unroll
                for (int nt = 0; nt < 4; nt++)
                    mma8(acc[mt][nt], af[mt], bf[nt]);
        }
        __syncthreads();
    }

    #pragma unroll
    for (int mt = 0; mt < 4; mt++) {
        const int row0 = wm * 64 + mt * 16 + gid;
        #pragma unroll
        for (int nt = 0; nt < 4; nt++) {
            const int col = wn * 32 + nt * 8 + tig * 2;
            float d0 = 1.f, d1 = 1.f;
            if (is_lt) {
                const int gcol = blockIdx.x * 128 + col;
                d0 = __ldg(diag + gcol); d1 = __ldg(diag + gcol + 1);
            }
            float2 v0, v1;
            v0.x = __uint_as_float(f2tf32(tanhf(acc[mt][nt][0]) * d0));
            v0.y = __uint_as_float(f2tf32(tanhf(acc[mt][nt][1]) * d1));
            v1.x = __uint_as_float(f2tf32(tanhf(acc[mt][nt][2]) * d0));
            v1.y = __uint_as_float(f2tf32(tanhf(acc[mt][nt][3]) * d1));
            *reinterpret_cast<float2*>(C + (size_t)row0 * DD + col) = v0;
            *reinterpret_cast<float2*>(C + (size_t)(row0 + 8) * DD + col) = v1;
        }
    }
}

// ---------------------------------------------------------------------------
// Fused scores + softmax.
// CTA = 64 L-rows x full R=512, K=256.  grid = (SEQ/64, BB).
// A (64x256 fp32) resident in smem; B streamed in 128-col chunks (BK=16,
// double buffered); scores accumulated into a 64x516 smem buffer; softmax
// from smem straight to global out.  No g_sc round trip.
// ---------------------------------------------------------------------------
#define PA 260            // A pitch (floats)
#define PS 516            // scores pitch (floats); 516*4 bytes = 16B-aligned
#define FS_SMEM_FLOATS (64 * PA + 64 * PS + 2 * 128 * PITCH)

__global__ __launch_bounds__(256, 1) void scores_softmax(float* __restrict__ out)
{
    extern __shared__ float sm[];
    float* Ar = sm;                       // 64 x PA
    float* Ss = sm + 64 * PA;             // 64 x PS
    float* Bs = Ss + 64 * PS;             // 2 x 128 x PITCH

    const int tid = threadIdx.x, lane = tid & 31, wid = tid >> 5;
    const int gid = lane >> 2, tig = lane & 3;
    const int wm = wid & 1, wn = wid >> 1;
    const int b = blockIdx.y;

    const float* Lt = g_lt + (size_t)b * SEQ * DD + (size_t)blockIdx.x * 64 * DD;
    const float* Rt = g_rt + (size_t)b * SEQ * DD;

    // Load resident A: 64 rows x 256 cols (64 KB).
    // 4 threads per row; each thread loads 16 float4 chunks -> 64 chunks/row.
    {
        const int ar = tid >> 2;          // 0..63
        const int ch = tid & 3;           // chunk lane within row
        #pragma unroll
        for (int it = 0; it < 16; it++) {
            const int col = (ch + it * 4) * 4;   // 0..252 step 16 per lane
            cp16(smem_u32(&Ar[ar * PA + col]), Lt + (size_t)ar * DD + col);
        }
        CP_COMMIT();
    }

    const int r_ld0 = tid >> 2;
    const int kq_ld = tid & 3;
    auto load_b = [&](int nc, int kt, int buf) {
        const int kb = kt * 16;
        #pragma unroll
        for (int j = 0; j < 2; j++) {
            const int r = r_ld0 + j * 64;
            cp16(smem_u32(&Bs[buf * 128 * PITCH + r * PITCH + kq_ld * 4]),
                 Rt + (size_t)(nc * 128 + r) * DD + kb + kq_ld * 4);
        }
        CP_COMMIT();
    };

    constexpr int NK = DD / 16;           // 16

    #pragma unroll 1
    for (int nc = 0; nc < 4; nc++) {      // 4 chunks of 128 R-cols
        float acc[2][4][4];
        #pragma unroll
        for (int mt = 0; mt < 2; mt++)
            #pragma unroll
            for (int nt = 0; nt < 4; nt++)
                #pragma unroll
                for (int c = 0; c < 4; c++) acc[mt][nt][c] = 0.f;

        load_b(nc, 0, 0);

        #pragma unroll 1
        for (int kt = 0; kt < NK; kt++) {
            const int cur = kt & 1;
            if (kt + 1 < NK) { load_b(nc, kt + 1, cur ^ 1); CP_WAIT(1); }
            else             { CP_WAIT(0); }
            __syncthreads();

            const int kb = kt * 16;
            #pragma unroll
            for (int ks = 0; ks < 2; ks++) {
                uint32_t af[2][4], bf[4][2];
                const int c0 = kb + ks * 8 + tig;
                #pragma unroll
                for (int mt = 0; mt < 2; mt++) {
                    const int r = (wm * 32 + mt * 16 + gid) * PA;
                    af[mt][0] = __float_as_uint(Ar[r + c0]);
                    af[mt][1] = __float_as_uint(Ar[r + 8 * PA + c0]);
                    af[mt][2] = __float_as_uint(Ar[r + c0 + 4]);
                    af[mt][3] = __float_as_uint(Ar[r + 8 * PA + c0 + 4]);
                }
                const int bc0 = ks * 8 + tig;
                #pragma unroll
                for (int nt = 0; nt < 4; nt++) {
                    const int r = cur * 128 * PITCH + (wn * 32 + nt * 8 + gid) * PITCH;
                    bf[nt][0] = __float_as_uint(Bs[r + bc0]);
                    bf[nt][1] = __float_as_uint(Bs[r + bc0 + 4]);
                }
                #pragma unroll
                for (int mt = 0; mt < 2; mt++)
                    #pragma unroll
                    for (int nt = 0; nt < 4; nt++)
                        mma8(acc[mt][nt], af[mt], bf[nt]);
            }
            __syncthreads();
        }

        // dump acc -> scores smem
        #pragma unroll
        for (int mt = 0; mt < 2; mt++) {
            const int row0 = wm * 32 + mt * 16 + gid;
            #pragma unroll
            for (int nt = 0; nt < 4; nt++) {
                const int col = nc * 128 + wn * 32 + nt * 8 + tig * 2;
                Ss[row0 * PS + col]       = acc[mt][nt][0];
                Ss[row0 * PS + col + 1]   = acc[mt][nt][1];
                Ss[(row0 + 8) * PS + col]     = acc[mt][nt][2];
                Ss[(row0 + 8) * PS + col + 1] = acc[mt][nt][3];
            }
        }
    }
    __syncthreads();

    // ---- softmax from smem: warp w handles rows w*8 .. w*8+7 ----
    const size_t orow0 = ((size_t)b * SEQ + (size_t)blockIdx.x * 64);
    #pragma unroll 1
    for (int rr = 0; rr < 8; rr++) {
        const int row = wid * 8 + rr;
        float4 v[4];
        #pragma unroll
        for (int i = 0; i < 4; i++)
            v[i] = *reinterpret_cast<const float4*>(&Ss[row * PS + lane * 4 + i * 128]);

        float m = -1e30f;
        #pragma unroll
        for (int i = 0; i < 4; i++)
            m = fmaxf(m, fmaxf(fmaxf(v[i].x, v[i].y), fmaxf(v[i].z, v[i].w)));
        #pragma unroll
        for (int off = 16; off; off >>= 1)
            m = fmaxf(m, __shfl_xor_sync(0xffffffffu, m, off));

        float s = 0.f;
        #pragma unroll
        for (int i = 0; i < 4; i++) {
            v[i].x = __expf(v[i].x - m); v[i].y = __expf(v[i].y - m);
            v[i].z = __expf(v[i].z - m); v[i].w = __expf(v[i].w - m);
            s += v[i].x + v[i].y + v[i].z + v[i].w;
        }
        #pragma unroll
        for (int off = 16; off; off >>= 1)
            s += __shfl_xor_sync(0xffffffffu, s, off);
        const float inv = 1.f / s;

        float* op = out + (orow0 + row) * SEQ;
        #pragma unroll
        for (int i = 0; i < 4; i++) {
            float4 o = make_float4(v[i].x * inv, v[i].y * inv, v[i].z * inv, v[i].w * inv);
            *reinterpret_cast<float4*>(op + lane * 4 + i * 128) = o;
        }
    }
}

// ---------------------------------------------------------------------------
// W transpose (H,D) -> (D,H), pre-rounded to tf32.
// ---------------------------------------------------------------------------
__global__ void transpose_w(const float* __restrict__ W, float* __restrict__ Wt) {
    __shared__ float t[32][33];
    const int d0 = blockIdx.x * 32, h0 = blockIdx.y * 32;
    for (int i = threadIdx.y; i < 32; i += 8)
        t[i][threadIdx.x] = W[(size_t)(h0 + i) * DD + d0 + threadIdx.x];
    __syncthreads();
    for (int i = threadIdx.y; i < 32; i += 8)
        Wt[(size_t)(d0 + i) * HH + h0 + threadIdx.x] =
            __uint_as_float(f2tf32(t[threadIdx.x][i]));
}

// ---------------------------------------------------------------------------
extern "C" void kernel_launch(void* const* d_in, const int* in_sizes, int n_in,
                              void* d_out, int out_size)
{
    const float* lt = (const float*)d_in[0];   // (B, L, H)
    const float* rt = (const float*)d_in[1];   // (B, R, H)
    const float* W  = (const float*)d_in[2];   // (H, D)
    const float* dg = (const float*)d_in[3];   // (1, 1, D)
    float* out = (float*)d_out;                // (B, L, R)

    float *p_lt, *p_rt, *p_wt;
    cudaGetSymbolAddress((void**)&p_lt, g_lt);
    cudaGetSymbolAddress((void**)&p_rt, g_rt);
    cudaGetSymbolAddress((void**)&p_wt, g_wt);

    transpose_w<<<dim3(DD / 32, HH / 32), dim3(32, 8)>>>(W, p_wt);

    // Both projections in one launch: grid (2, 512)
    proj_tc<<<dim3(2, 512), 256>>>(lt, rt, dg, p_lt, p_rt);

    // Fused scores + softmax
    const int FS_BYTES = FS_SMEM_FLOATS * 4;   // 219136
    cudaFuncSetAttribute(scores_softmax,
                         cudaFuncAttributeMaxDynamicSharedMemorySize, FS_BYTES);
    scores_softmax<<<dim3(SEQ / 64, BB), 256, FS_BYTES>>>(out);
}